// round 4
// baseline (speedup 1.0000x reference)
#include <cuda_runtime.h>
#include <cuda_bf16.h>
#include <cstdint>
#include <cstddef>

// ---------------- problem dims ----------------
#define BB 4096
#define DD 1024
#define HH 4096
#define OO 1024
#define NE 8
#define NAE 5

// ---------------- device scratch ----------------
__device__ __nv_bfloat16 g_x2[(size_t)BB * 2 * DD];
__device__ __nv_bfloat16 g_w1s[(size_t)NE * HH * 2 * DD];
__device__ __nv_bfloat16 g_w2s[(size_t)NE * OO * 2 * HH];
__device__ __nv_bfloat16 g_hs[(size_t)NE * BB * 2 * HH];
__device__ float g_gw[(size_t)BB * NE];
__device__ float g_part[(size_t)4 * BB * OO];   // layer-2 split-K partials

// ---------------- helpers ----------------
__device__ __forceinline__ uint32_t smem_u32(const void* p) {
    uint32_t a;
    asm("{ .reg .u64 t; cvta.to.shared.u64 t, %1; cvt.u32.u64 %0, t; }" : "=r"(a) : "l"(p));
    return a;
}
#define SWZ(off) ((off) ^ (((off) >> 3) & 0x70))

__device__ __forceinline__ void cp_async16(uint32_t saddr, const void* gptr) {
    asm volatile("cp.async.cg.shared.global [%0], [%1], 16;\n" :: "r"(saddr), "l"(gptr));
}
__device__ __forceinline__ void cp_commit() {
    asm volatile("cp.async.commit_group;\n" ::: "memory");
}
template <int N>
__device__ __forceinline__ void cp_wait() {
    asm volatile("cp.async.wait_group %0;\n" :: "n"(N) : "memory");
}
__device__ __forceinline__ void ldsm_x4(uint32_t& r0, uint32_t& r1, uint32_t& r2,
                                        uint32_t& r3, uint32_t addr) {
    asm volatile("ldmatrix.sync.aligned.m8n8.x4.shared.b16 {%0,%1,%2,%3}, [%4];"
                 : "=r"(r0), "=r"(r1), "=r"(r2), "=r"(r3) : "r"(addr));
}
__device__ __forceinline__ void mma16816(float* c, const uint32_t* a, const uint32_t* b) {
    asm volatile(
        "mma.sync.aligned.m16n8k16.row.col.f32.bf16.bf16.f32 "
        "{%0,%1,%2,%3}, {%4,%5,%6,%7}, {%8,%9}, {%0,%1,%2,%3};"
        : "+f"(c[0]), "+f"(c[1]), "+f"(c[2]), "+f"(c[3])
        : "r"(a[0]), "r"(a[1]), "r"(a[2]), "r"(a[3]), "r"(b[0]), "r"(b[1]));
}

// ---------------- gate kernel ----------------
__global__ void gate_kernel(const float* __restrict__ x, const float* __restrict__ Wg,
                            const float* __restrict__ bg, float* __restrict__ gw) {
    __shared__ float slog[NE];
    int b = blockIdx.x;
    int wid = threadIdx.x >> 5, lid = threadIdx.x & 31;
    const float* xr = x + (size_t)b * DD;
    const float* wr = Wg + (size_t)wid * DD;
    float s = 0.f;
    for (int i = lid; i < DD; i += 32) s += xr[i] * wr[i];
#pragma unroll
    for (int o = 16; o > 0; o >>= 1) s += __shfl_xor_sync(0xffffffffu, s, o);
    if (lid == 0) slog[wid] = s + bg[wid];
    __syncthreads();
    if (threadIdx.x == 0) {
        const float invT = 0.36787944117144233f;
        float l[NE], mx = -1e30f;
#pragma unroll
        for (int i = 0; i < NE; i++) { l[i] = slog[i] * invT; mx = fmaxf(mx, l[i]); }
        float p[NE], se = 0.f;
#pragma unroll
        for (int i = 0; i < NE; i++) { p[i] = expf(l[i] - mx); se += p[i]; }
        float inv_se = 1.f / se;
#pragma unroll
        for (int i = 0; i < NE; i++) p[i] *= inv_se;
        bool sel[NE];
#pragma unroll
        for (int i = 0; i < NE; i++) sel[i] = false;
        float ss = 0.f;
        for (int it = 0; it < NAE; it++) {
            int bi = 0; float bv = -1.f;
#pragma unroll
            for (int i = 0; i < NE; i++)
                if (!sel[i] && p[i] > bv) { bv = p[i]; bi = i; }
            sel[bi] = true; ss += bv;
        }
        float inv = 1.f / (ss + 1e-8f);
#pragma unroll
        for (int i = 0; i < NE; i++)
            gw[(size_t)b * NE + i] = sel[i] ? p[i] * inv : 0.f;
    }
}

// ---------------- fp32 -> bf16 hi/lo split ----------------
__global__ void split_kernel(const float* __restrict__ in, __nv_bfloat16* __restrict__ out,
                             int K, size_t total) {
    size_t n4 = total >> 2;
    size_t i = (size_t)blockIdx.x * blockDim.x + threadIdx.x;
    size_t str = (size_t)gridDim.x * blockDim.x;
    for (; i < n4; i += str) {
        size_t idx = i << 2;
        size_t r = idx / (size_t)K;
        int c = (int)(idx - r * (size_t)K);
        float4 v = reinterpret_cast<const float4*>(in)[i];
        float vv[4] = {v.x, v.y, v.z, v.w};
        __nv_bfloat16 hb[4], lb[4];
#pragma unroll
        for (int j = 0; j < 4; j++) {
            hb[j] = __float2bfloat16(vv[j]);
            lb[j] = __float2bfloat16(vv[j] - __bfloat162float(hb[j]));
        }
        size_t base = r * (size_t)(2 * K) + c;
        *reinterpret_cast<uint2*>(out + base)     = *reinterpret_cast<uint2*>(hb);
        *reinterpret_cast<uint2*>(out + base + K) = *reinterpret_cast<uint2*>(lb);
    }
}

// ---------------- GEMM config: 128x256 tile, BK=32, hi/lo fused per chunk ----------------
#define BM 128
#define BN 256
#define BK 32
#define TPB 256
#define A_STAGE 16384          // 128 rows x 128B ([hi 64B | lo 64B])
#define B_STAGE 32768          // 256 rows x 128B
#define B_OFF   (4 * A_STAGE)  // 65536
#define SMEM_GEMM (4 * A_STAGE + 4 * B_STAGE)   // 196608

// fragment compute core shared by both GEMMs (term-fused):
//   acc += Ahi*Bhi + Ahi*Blo + Alo*Bhi  for one BK=32 chunk in stage s
struct Frags { float acc[2][8][4]; };  // [mf][nf][4], warp tile 32?? -> see below

// NOTE: warp tile is 64(m) x 64(n): mf in [0,4), nf in [0,8). acc[4][8][4]=128 floats.

__device__ __forceinline__ void compute_stage_core(
    uint32_t sbase, int s, int warp_m, int warp_n, int lid, float acc[4][8][4]) {
    uint32_t aBase = sbase + s * A_STAGE;
    uint32_t bBase = sbase + B_OFF + s * B_STAGE;
    int rA = warp_m * 64 + (lid & 15);
    int rB = warp_n * 64 + (lid & 15);
    int kh = (lid >> 4) * 16;
#pragma unroll
    for (int ksub = 0; ksub < 2; ksub++) {
        int cHi = ksub * 32 + kh;        // hi bytes [0,64)
        int cLo = 64 + ksub * 32 + kh;   // lo bytes [64,128)
        uint32_t a_hi[4][4], a_lo[4][4];
        uint32_t b_hi[8][2], b_lo[8][2];
#pragma unroll
        for (int mf = 0; mf < 4; mf++) {
            ldsm_x4(a_hi[mf][0], a_hi[mf][1], a_hi[mf][2], a_hi[mf][3],
                    aBase + SWZ((uint32_t)((rA + mf * 16) * 128 + cHi)));
        }
#pragma unroll
        for (int pr = 0; pr < 4; pr++) {
            uint32_t r0, r1, r2, r3;
            ldsm_x4(r0, r1, r2, r3, bBase + SWZ((uint32_t)((rB + pr * 16) * 128 + cHi)));
            b_hi[pr * 2 + 0][0] = r0; b_hi[pr * 2 + 1][0] = r1;
            b_hi[pr * 2 + 0][1] = r2; b_hi[pr * 2 + 1][1] = r3;
        }
        // t0: Ahi x Bhi
#pragma unroll
        for (int mf = 0; mf < 4; mf++)
#pragma unroll
            for (int nf = 0; nf < 8; nf++)
                mma16816(acc[mf][nf], a_hi[mf], b_hi[nf]);
        // t1: Ahi x Blo
#pragma unroll
        for (int pr = 0; pr < 4; pr++) {
            uint32_t r0, r1, r2, r3;
            ldsm_x4(r0, r1, r2, r3, bBase + SWZ((uint32_t)((rB + pr * 16) * 128 + cLo)));
            b_lo[pr * 2 + 0][0] = r0; b_lo[pr * 2 + 1][0] = r1;
            b_lo[pr * 2 + 0][1] = r2; b_lo[pr * 2 + 1][1] = r3;
        }
#pragma unroll
        for (int mf = 0; mf < 4; mf++)
#pragma unroll
            for (int nf = 0; nf < 8; nf++)
                mma16816(acc[mf][nf], a_hi[mf], b_lo[nf]);
        // t2: Alo x Bhi
#pragma unroll
        for (int mf = 0; mf < 4; mf++) {
            ldsm_x4(a_lo[mf][0], a_lo[mf][1], a_lo[mf][2], a_lo[mf][3],
                    aBase + SWZ((uint32_t)((rA + mf * 16) * 128 + cLo)));
        }
#pragma unroll
        for (int mf = 0; mf < 4; mf++)
#pragma unroll
            for (int nf = 0; nf < 8; nf++)
                mma16816(acc[mf][nf], a_lo[mf], b_hi[nf]);
    }
}

// load one BK=32 chunk (hi+lo for A and B) into stage s
__device__ __forceinline__ void load_stage_core(
    uint32_t sbase, int s, int tid,
    const __nv_bfloat16* __restrict__ Ab, int lo_offA,   // Ab: row base ptr at (m0, kk)
    const __nv_bfloat16* __restrict__ Bb, int lo_offB,
    int ldA, int ldB) {
    uint32_t sa = sbase + s * A_STAGE;
    uint32_t sb = sbase + B_OFF + s * B_STAGE;
#pragma unroll
    for (int i = 0; i < 4; i++) {   // A: 1024 x 16B
        int u = tid + i * TPB;
        int r = u >> 3, seg = u & 7;
        uint32_t off = SWZ((uint32_t)(r * 128 + seg * 16));
        const __nv_bfloat16* g = Ab + (size_t)r * ldA +
                                 ((seg & 4) ? lo_offA + (seg & 3) * 8 : (seg & 3) * 8);
        cp_async16(sa + off, g);
    }
#pragma unroll
    for (int i = 0; i < 8; i++) {   // B: 2048 x 16B
        int u = tid + i * TPB;
        int r = u >> 3, seg = u & 7;
        uint32_t off = SWZ((uint32_t)(r * 128 + seg * 16));
        const __nv_bfloat16* g = Bb + (size_t)r * ldB +
                                 ((seg & 4) ? lo_offB + (seg & 3) * 8 : (seg & 3) * 8);
        cp_async16(sb + off, g);
    }
}

// ===================== layer-1 GEMM =====================
__global__ __launch_bounds__(TPB, 1) void gemm1_kernel(
    const __nv_bfloat16* __restrict__ A,          // x2 [BB][2*DD]
    const __nv_bfloat16* __restrict__ Wbase,      // w1s [NE][HH][2*DD]
    const float* __restrict__ b1,
    const float* __restrict__ gw,
    __nv_bfloat16* __restrict__ hsBase) {
    extern __shared__ __align__(1024) char smem[];
    uint32_t sbase = smem_u32(smem);
    int tid = threadIdx.x, lid = tid & 31, wid = tid >> 5;
    int warp_m = wid >> 2, warp_n = wid & 3;
    int n0 = blockIdx.x * BN, m0 = blockIdx.y * BM;
    int z = blockIdx.z;
    const int ldA = 2 * DD, ldB = 2 * DD;
    const int NC = DD / BK;     // 32

    const __nv_bfloat16* Bm = Wbase + (size_t)z * HH * ldB;

    float acc[4][8][4];
#pragma unroll
    for (int a = 0; a < 4; a++)
#pragma unroll
        for (int b = 0; b < 8; b++)
#pragma unroll
            for (int c = 0; c < 4; c++) acc[a][b][c] = 0.f;

    auto issue = [&](int ci) {
        load_stage_core(sbase, ci & 3, tid,
                        A + (size_t)m0 * ldA + ci * BK, DD,
                        Bm + (size_t)n0 * ldB + ci * BK, DD, ldA, ldB);
        cp_commit();
    };

    issue(0); issue(1); issue(2);
    for (int ci = 0; ci < NC; ci++) {
        int rem = NC - 1 - ci;
        if (rem >= 2) cp_wait<2>(); else if (rem == 1) cp_wait<1>(); else cp_wait<0>();
        __syncthreads();
        if (ci + 3 < NC) issue(ci + 3);
        compute_stage_core(sbase, ci & 3, warp_m, warp_n, lid, acc);
    }

    // epilogue: bias + relu, gw-scale, hi/lo split -> hs
    int g = lid >> 2, t4 = lid & 3;
    const float* bias = b1 + (size_t)z * HH;
    __nv_bfloat16* hs = hsBase + (size_t)z * BB * (2 * HH);
#pragma unroll
    for (int mf = 0; mf < 4; mf++) {
#pragma unroll
        for (int h = 0; h < 2; h++) {
            int row = m0 + warp_m * 64 + mf * 16 + g + h * 8;
            float wv = gw[(size_t)row * NE + z];
#pragma unroll
            for (int nf = 0; nf < 8; nf++) {
                int col = n0 + warp_n * 64 + nf * 8 + t4 * 2;
                float2 bz = *reinterpret_cast<const float2*>(bias + col);
                float v0 = fmaxf(acc[mf][nf][h * 2 + 0] + bz.x, 0.f) * wv;
                float v1 = fmaxf(acc[mf][nf][h * 2 + 1] + bz.y, 0.f) * wv;
                __nv_bfloat16 h0 = __float2bfloat16(v0);
                __nv_bfloat16 h1 = __float2bfloat16(v1);
                __nv_bfloat16 l0 = __float2bfloat16(v0 - __bfloat162float(h0));
                __nv_bfloat16 l1 = __float2bfloat16(v1 - __bfloat162float(h1));
                uint32_t hp = ((uint32_t)__bfloat16_as_ushort(h1) << 16) |
                              (uint32_t)__bfloat16_as_ushort(h0);
                uint32_t lp = ((uint32_t)__bfloat16_as_ushort(l1) << 16) |
                              (uint32_t)__bfloat16_as_ushort(l0);
                size_t base = (size_t)row * (2 * HH) + col;
                *reinterpret_cast<uint32_t*>(hs + base) = hp;
                *reinterpret_cast<uint32_t*>(hs + base + HH) = lp;
            }
        }
    }
}

// ===================== layer-2 GEMM (split-K over expert pairs) =====================
__global__ __launch_bounds__(TPB, 1) void gemm2_kernel(
    const __nv_bfloat16* __restrict__ hsBase,     // [NE][BB][2*HH]
    const __nv_bfloat16* __restrict__ Wbase,      // w2s [NE][OO][2*HH]
    float* __restrict__ part) {                   // [4][BB][OO]
    extern __shared__ __align__(1024) char smem[];
    uint32_t sbase = smem_u32(smem);
    int tid = threadIdx.x, lid = tid & 31, wid = tid >> 5;
    int warp_m = wid >> 2, warp_n = wid & 3;
    int n0 = blockIdx.x * BN, m0 = blockIdx.y * BM;
    int sidx = blockIdx.z;                 // expert pair {2s, 2s+1}
    const int ldA = 2 * HH, ldB = 2 * HH;
    const int KCZ = HH / BK;               // 128 chunks per expert
    const int NC = 2 * KCZ;                // 256

    float acc[4][8][4];
#pragma unroll
    for (int a = 0; a < 4; a++)
#pragma unroll
        for (int b = 0; b < 8; b++)
#pragma unroll
            for (int c = 0; c < 4; c++) acc[a][b][c] = 0.f;

    auto issue = [&](int ci) {
        int z = 2 * sidx + (ci >> 7);
        int kk = (ci & (KCZ - 1)) * BK;
        const __nv_bfloat16* Ab = hsBase + (size_t)z * BB * ldA + (size_t)m0 * ldA + kk;
        const __nv_bfloat16* Bb = Wbase + (size_t)z * OO * ldB + (size_t)n0 * ldB + kk;
        load_stage_core(sbase, ci & 3, tid, Ab, HH, Bb, HH, ldA, ldB);
        cp_commit();
    };

    issue(0); issue(1); issue(2);
    for (int ci = 0; ci < NC; ci++) {
        int rem = NC - 1 - ci;
        if (rem >= 2) cp_wait<2>(); else if (rem == 1) cp_wait<1>(); else cp_wait<0>();
        __syncthreads();
        if (ci + 3 < NC) issue(ci + 3);
        compute_stage_core(sbase, ci & 3, warp_m, warp_n, lid, acc);
    }

    // epilogue: raw partial write (bias handled in reduce)
    int g = lid >> 2, t4 = lid & 3;
    float* pp = part + (size_t)sidx * BB * OO;
#pragma unroll
    for (int mf = 0; mf < 4; mf++) {
#pragma unroll
        for (int h = 0; h < 2; h++) {
            int row = m0 + warp_m * 64 + mf * 16 + g + h * 8;
#pragma unroll
            for (int nf = 0; nf < 8; nf++) {
                int col = n0 + warp_n * 64 + nf * 8 + t4 * 2;
                float2 o;
                o.x = acc[mf][nf][h * 2 + 0];
                o.y = acc[mf][nf][h * 2 + 1];
                *reinterpret_cast<float2*>(pp + (size_t)row * OO + col) = o;
            }
        }
    }
}

// ===================== reduce: out = sum_s part[s] + sum_z gw*b2 =====================
__global__ void reduce_kernel(const float* __restrict__ part, const float* __restrict__ b2,
                              const float* __restrict__ gw, float* __restrict__ out) {
    const size_t n4 = (size_t)BB * OO / 4;
    size_t i = (size_t)blockIdx.x * blockDim.x + threadIdx.x;
    if (i >= n4) return;
    size_t b = i / (OO / 4);
    int o4 = (int)(i - b * (OO / 4));
    float4 a0 = reinterpret_cast<const float4*>(part)[i];
    float4 a1 = reinterpret_cast<const float4*>(part)[n4 + i];
    float4 a2 = reinterpret_cast<const float4*>(part)[2 * n4 + i];
    float4 a3 = reinterpret_cast<const float4*>(part)[3 * n4 + i];
    float4 acc;
    acc.x = (a0.x + a1.x) + (a2.x + a3.x);
    acc.y = (a0.y + a1.y) + (a2.y + a3.y);
    acc.z = (a0.z + a1.z) + (a2.z + a3.z);
    acc.w = (a0.w + a1.w) + (a2.w + a3.w);
#pragma unroll
    for (int z = 0; z < NE; z++) {
        float wv = gw[b * NE + z];
        float4 bz = reinterpret_cast<const float4*>(b2)[(size_t)z * (OO / 4) + o4];
        acc.x += wv * bz.x; acc.y += wv * bz.y;
        acc.z += wv * bz.z; acc.w += wv * bz.w;
    }
    reinterpret_cast<float4*>(out)[i] = acc;
}

// ---------------- host launcher ----------------
extern "C" void kernel_launch(void* const* d_in, const int* in_sizes, int n_in,
                              void* d_out, int out_size) {
    const float* x  = (const float*)d_in[0];
    const float* W1 = (const float*)d_in[1];
    const float* b1 = (const float*)d_in[2];
    const float* W2 = (const float*)d_in[3];
    const float* b2 = (const float*)d_in[4];
    const float* Wg = (const float*)d_in[5];
    const float* bg = (const float*)d_in[6];
    float* out = (float*)d_out;

    void *px2, *pw1s, *pw2s, *phs, *pgw, *ppart;
    cudaGetSymbolAddress(&px2, g_x2);
    cudaGetSymbolAddress(&pw1s, g_w1s);
    cudaGetSymbolAddress(&pw2s, g_w2s);
    cudaGetSymbolAddress(&phs, g_hs);
    cudaGetSymbolAddress(&pgw, g_gw);
    cudaGetSymbolAddress(&ppart, g_part);

    cudaFuncSetAttribute(gemm1_kernel, cudaFuncAttributeMaxDynamicSharedMemorySize, SMEM_GEMM);
    cudaFuncSetAttribute(gemm2_kernel, cudaFuncAttributeMaxDynamicSharedMemorySize, SMEM_GEMM);

    gate_kernel<<<BB, 256>>>(x, Wg, bg, (float*)pgw);
    split_kernel<<<4096, 256>>>(x, (__nv_bfloat16*)px2, DD, (size_t)BB * DD);
    split_kernel<<<16384, 256>>>(W1, (__nv_bfloat16*)pw1s, DD, (size_t)NE * HH * DD);
    split_kernel<<<16384, 256>>>(W2, (__nv_bfloat16*)pw2s, HH, (size_t)NE * OO * HH);

    gemm1_kernel<<<dim3(HH / BN, BB / BM, NE), TPB, SMEM_GEMM>>>(
        (const __nv_bfloat16*)px2, (const __nv_bfloat16*)pw1s, b1,
        (const float*)pgw, (__nv_bfloat16*)phs);

    gemm2_kernel<<<dim3(OO / BN, BB / BM, 4), TPB, SMEM_GEMM>>>(
        (const __nv_bfloat16*)phs, (const __nv_bfloat16*)pw2s, (float*)ppart);

    reduce_kernel<<<(BB * OO / 4 + 255) / 256, 256>>>(
        (const float*)ppart, b2, (const float*)pgw, out);
}

// round 5
// speedup vs baseline: 2.5133x; 2.5133x over previous
#include <cuda_runtime.h>
#include <cuda_fp16.h>
#include <cstdint>
#include <cstddef>

// ---------------- problem dims ----------------
#define BB 4096
#define DD 1024
#define HH 4096
#define OO 1024
#define NE 8
#define NAE 5

// ---------------- device scratch ----------------
__device__ __half g_x16[(size_t)BB * DD];                 // x rounded to fp16
__device__ __half g_w1s[(size_t)NE * HH * 2 * DD];        // W1 fp16 [hi D | lo D]
__device__ __half g_w2s[(size_t)NE * OO * 2 * HH];        // W2 fp16 [hi H | lo H]
__device__ __half g_h16[(size_t)NE * BB * HH];            // compacted gw-scaled h (fp16)
__device__ float g_part[(size_t)NE * BB * OO];            // per-expert layer-2 partials
__device__ float g_gw[(size_t)BB * NE];
__device__ int g_list[(size_t)NE * BB];
__device__ int g_cnt[NE];

// ---------------- helpers ----------------
__device__ __forceinline__ uint32_t smem_u32(const void* p) {
    uint32_t a;
    asm("{ .reg .u64 t; cvta.to.shared.u64 t, %1; cvt.u32.u64 %0, t; }" : "=r"(a) : "l"(p));
    return a;
}
#define SWZ(off) ((off) ^ (((off) >> 3) & 0x70))

__device__ __forceinline__ void cp_async16(uint32_t saddr, const void* gptr) {
    asm volatile("cp.async.cg.shared.global [%0], [%1], 16;\n" :: "r"(saddr), "l"(gptr));
}
__device__ __forceinline__ void cp_commit() {
    asm volatile("cp.async.commit_group;\n" ::: "memory");
}
template <int N>
__device__ __forceinline__ void cp_wait() {
    asm volatile("cp.async.wait_group %0;\n" :: "n"(N) : "memory");
}
__device__ __forceinline__ void ldsm_x4(uint32_t& r0, uint32_t& r1, uint32_t& r2,
                                        uint32_t& r3, uint32_t addr) {
    asm volatile("ldmatrix.sync.aligned.m8n8.x4.shared.b16 {%0,%1,%2,%3}, [%4];"
                 : "=r"(r0), "=r"(r1), "=r"(r2), "=r"(r3) : "r"(addr));
}
__device__ __forceinline__ void mma16816(float* c, const uint32_t* a, const uint32_t* b) {
    asm volatile(
        "mma.sync.aligned.m16n8k16.row.col.f32.f16.f16.f32 "
        "{%0,%1,%2,%3}, {%4,%5,%6,%7}, {%8,%9}, {%0,%1,%2,%3};"
        : "+f"(c[0]), "+f"(c[1]), "+f"(c[2]), "+f"(c[3])
        : "r"(a[0]), "r"(a[1]), "r"(a[2]), "r"(a[3]), "r"(b[0]), "r"(b[1]));
}

// ---------------- gate kernel (fp32, exact semantics) ----------------
__global__ void gate_kernel(const float* __restrict__ x, const float* __restrict__ Wg,
                            const float* __restrict__ bg, float* __restrict__ gw) {
    __shared__ float slog[NE];
    int b = blockIdx.x;
    int wid = threadIdx.x >> 5, lid = threadIdx.x & 31;
    const float* xr = x + (size_t)b * DD;
    const float* wr = Wg + (size_t)wid * DD;
    float s = 0.f;
    for (int i = lid; i < DD; i += 32) s += xr[i] * wr[i];
#pragma unroll
    for (int o = 16; o > 0; o >>= 1) s += __shfl_xor_sync(0xffffffffu, s, o);
    if (lid == 0) slog[wid] = s + bg[wid];
    __syncthreads();
    if (threadIdx.x == 0) {
        const float invT = 0.36787944117144233f;
        float l[NE], mx = -1e30f;
#pragma unroll
        for (int i = 0; i < NE; i++) { l[i] = slog[i] * invT; mx = fmaxf(mx, l[i]); }
        float p[NE], se = 0.f;
#pragma unroll
        for (int i = 0; i < NE; i++) { p[i] = expf(l[i] - mx); se += p[i]; }
        float inv_se = 1.f / se;
#pragma unroll
        for (int i = 0; i < NE; i++) p[i] *= inv_se;
        bool sel[NE];
#pragma unroll
        for (int i = 0; i < NE; i++) sel[i] = false;
        float ss = 0.f;
        for (int it = 0; it < NAE; it++) {
            int bi = 0; float bv = -1.f;
#pragma unroll
            for (int i = 0; i < NE; i++)
                if (!sel[i] && p[i] > bv) { bv = p[i]; bi = i; }
            sel[bi] = true; ss += bv;
        }
        float inv = 1.f / (ss + 1e-8f);
#pragma unroll
        for (int i = 0; i < NE; i++)
            gw[(size_t)b * NE + i] = sel[i] ? p[i] * inv : 0.f;
    }
}

// ---------------- per-expert token list (deterministic, token order) ----------------
__global__ void build_lists(const float* __restrict__ gw, int* __restrict__ list,
                            int* __restrict__ cnt) {
    int z = blockIdx.x, tid = threadIdx.x;
    __shared__ int sbase;
    __shared__ int wtot[8];
    if (tid == 0) sbase = 0;
    __syncthreads();
    for (int t0 = 0; t0 < BB; t0 += 256) {
        int b = t0 + tid;
        int act = gw[(size_t)b * NE + z] > 0.f;
        unsigned m = __ballot_sync(0xffffffffu, act);
        int wid = tid >> 5, lid = tid & 31;
        int wpre = __popc(m & ((1u << lid) - 1u));
        if (lid == 31) wtot[wid] = __popc(m);
        __syncthreads();
        int woff = 0;
        for (int w = 0; w < wid; w++) woff += wtot[w];
        if (act) list[(size_t)z * BB + sbase + woff + wpre] = b;
        __syncthreads();
        if (tid == 0) {
            int tot = 0;
            for (int w = 0; w < 8; w++) tot += wtot[w];
            sbase += tot;
        }
        __syncthreads();
    }
    int c = sbase;
    if (tid == 0) cnt[z] = c;
    int cpad = (c + 127) & ~127;
    for (int i = c + tid; i < cpad; i += 256) list[(size_t)z * BB + i] = 0;
}

// ---------------- conversions ----------------
__global__ void tohalf_kernel(const float* __restrict__ in, __half* __restrict__ out,
                              size_t n4) {
    size_t i = (size_t)blockIdx.x * blockDim.x + threadIdx.x;
    size_t str = (size_t)gridDim.x * blockDim.x;
    for (; i < n4; i += str) {
        float4 v = reinterpret_cast<const float4*>(in)[i];
        __half h[4] = {__float2half_rn(v.x), __float2half_rn(v.y),
                       __float2half_rn(v.z), __float2half_rn(v.w)};
        *reinterpret_cast<uint2*>(out + i * 4) = *reinterpret_cast<uint2*>(h);
    }
}

__global__ void splitw_kernel(const float* __restrict__ in, __half* __restrict__ out,
                              int K, size_t total) {
    size_t n4 = total >> 2;
    size_t i = (size_t)blockIdx.x * blockDim.x + threadIdx.x;
    size_t str = (size_t)gridDim.x * blockDim.x;
    for (; i < n4; i += str) {
        size_t idx = i << 2;
        size_t r = idx / (size_t)K;
        int c = (int)(idx - r * (size_t)K);
        float4 v = reinterpret_cast<const float4*>(in)[i];
        float vv[4] = {v.x, v.y, v.z, v.w};
        __half hb[4], lb[4];
#pragma unroll
        for (int j = 0; j < 4; j++) {
            hb[j] = __float2half_rn(vv[j]);
            lb[j] = __float2half_rn(vv[j] - __half2float(hb[j]));
        }
        size_t base = r * (size_t)(2 * K) + c;
        *reinterpret_cast<uint2*>(out + base)     = *reinterpret_cast<uint2*>(hb);
        *reinterpret_cast<uint2*>(out + base + K) = *reinterpret_cast<uint2*>(lb);
    }
}

// ---------------- GEMM config: 128x256 tile, BK=64, A fp16 single + B fp16 hi/lo ----
#define TPB 256
#define ST_SZ 81920            // A 16K + Bhi 32K + Blo 32K
#define BH_OFF 16384
#define BL_OFF 49152
#define ILIST_OFF (2 * ST_SZ)  // 163840
#define SMEM_SZ (2 * ST_SZ + 512)

// compute one BK=64 chunk: acc += A x (Bhi + Blo)
__device__ __forceinline__ void compute_chunk(uint32_t sbase, int s, int warp_m,
                                              int warp_n, int lid, float acc[4][8][4]) {
    uint32_t aB = sbase + s * ST_SZ;
    uint32_t hB = aB + BH_OFF;
    uint32_t lB = aB + BL_OFF;
    int rA = warp_m * 64 + (lid & 15);
    int rB = warp_n * 64 + (lid & 15);
    int kh = (lid >> 4) * 16;
#pragma unroll
    for (int ks = 0; ks < 4; ks++) {
        int colb = ks * 32 + kh;
        uint32_t a[4][4];
#pragma unroll
        for (int mf = 0; mf < 4; mf++)
            ldsm_x4(a[mf][0], a[mf][1], a[mf][2], a[mf][3],
                    aB + SWZ((uint32_t)((rA + mf * 16) * 128 + colb)));
        uint32_t bh[8][2];
#pragma unroll
        for (int pr = 0; pr < 4; pr++) {
            uint32_t r0, r1, r2, r3;
            ldsm_x4(r0, r1, r2, r3, hB + SWZ((uint32_t)((rB + pr * 16) * 128 + colb)));
            bh[pr * 2 + 0][0] = r0; bh[pr * 2 + 1][0] = r1;
            bh[pr * 2 + 0][1] = r2; bh[pr * 2 + 1][1] = r3;
        }
#pragma unroll
        for (int mf = 0; mf < 4; mf++)
#pragma unroll
            for (int nf = 0; nf < 8; nf++)
                mma16816(acc[mf][nf], a[mf], bh[nf]);
        uint32_t bl[8][2];
#pragma unroll
        for (int pr = 0; pr < 4; pr++) {
            uint32_t r0, r1, r2, r3;
            ldsm_x4(r0, r1, r2, r3, lB + SWZ((uint32_t)((rB + pr * 16) * 128 + colb)));
            bl[pr * 2 + 0][0] = r0; bl[pr * 2 + 1][0] = r1;
            bl[pr * 2 + 0][1] = r2; bl[pr * 2 + 1][1] = r3;
        }
#pragma unroll
        for (int mf = 0; mf < 4; mf++)
#pragma unroll
            for (int nf = 0; nf < 8; nf++)
                mma16816(acc[mf][nf], a[mf], bl[nf]);
    }
}

// B loader (hi+lo); wrow points at (row n0, col 0) of [hi D | lo D] matrix
__device__ __forceinline__ void load_B(uint32_t sbase, int s, int tid,
                                       const __half* __restrict__ wrow, int ldB,
                                       int DHALF, int kk) {
    uint32_t sh = sbase + s * ST_SZ + BH_OFF;
    uint32_t sl = sbase + s * ST_SZ + BL_OFF;
#pragma unroll
    for (int i = 0; i < 8; i++) {
        int u = tid + i * TPB;
        int r = u >> 3, seg = u & 7;
        uint32_t off = SWZ((uint32_t)(r * 128 + seg * 16));
        const __half* g = wrow + (size_t)r * ldB + kk + seg * 8;
        cp_async16(sh + off, g);
        cp_async16(sl + off, g + DHALF);
    }
}

// ===================== layer-1 GEMM (gathered A) =====================
__global__ __launch_bounds__(TPB, 1) void gemm1_kernel(
    const __half* __restrict__ x16,           // [BB][DD]
    const __half* __restrict__ w1s,           // [NE][HH][2*DD]
    const float* __restrict__ b1,             // [NE][HH]
    const float* __restrict__ gw,             // [BB][NE]
    const int* __restrict__ list, const int* __restrict__ cnt,
    __half* __restrict__ h16) {               // [NE][BB][HH] (compacted rows)
    int z = blockIdx.z;
    int m0 = blockIdx.y * 128;
    int cz = cnt[z];
    if (m0 >= cz) return;
    int n0 = blockIdx.x * 256;

    extern __shared__ __align__(1024) char smem[];
    uint32_t sbase = smem_u32(smem);
    int* silist = reinterpret_cast<int*>(smem + ILIST_OFF);
    int tid = threadIdx.x, lid = tid & 31, wid = tid >> 5;
    int warp_m = wid >> 2, warp_n = wid & 3;

    if (tid < 128) silist[tid] = list[(size_t)z * BB + m0 + tid];
    __syncthreads();

    const __half* wrow = w1s + (size_t)z * HH * (2 * DD) + (size_t)n0 * (2 * DD);
    const int NC = DD / 64;    // 16

    float acc[4][8][4];
#pragma unroll
    for (int a = 0; a < 4; a++)
#pragma unroll
        for (int b = 0; b < 8; b++)
#pragma unroll
            for (int c = 0; c < 4; c++) acc[a][b][c] = 0.f;

    auto issue = [&](int ci) {
        int s = ci & 1, kk = ci * 64;
        uint32_t sa = sbase + s * ST_SZ;
#pragma unroll
        for (int i = 0; i < 4; i++) {
            int u = tid + i * TPB;
            int r = u >> 3, seg = u & 7;
            int tok = silist[r];
            uint32_t off = SWZ((uint32_t)(r * 128 + seg * 16));
            cp_async16(sa + off, x16 + (size_t)tok * DD + kk + seg * 8);
        }
        load_B(sbase, s, tid, wrow, 2 * DD, DD, kk);
        cp_commit();
    };

    issue(0);
    for (int ci = 0; ci < NC; ci++) {
        if (ci + 1 < NC) { issue(ci + 1); cp_wait<1>(); } else { cp_wait<0>(); }
        __syncthreads();
        compute_chunk(sbase, ci & 1, warp_m, warp_n, lid, acc);
        __syncthreads();
    }

    // epilogue: bias + relu, gw-scale, round to fp16 -> h16[z][m0+row][col]
    int g = lid >> 2, t4 = lid & 3;
    const float* bias = b1 + (size_t)z * HH;
    __half* hz = h16 + (size_t)z * BB * HH;
#pragma unroll
    for (int mf = 0; mf < 4; mf++) {
#pragma unroll
        for (int h = 0; h < 2; h++) {
            int row_l = warp_m * 64 + mf * 16 + g + h * 8;
            int tok = silist[row_l];
            float wv = gw[(size_t)tok * NE + z];
            size_t rbase = (size_t)(m0 + row_l) * HH;
#pragma unroll
            for (int nf = 0; nf < 8; nf++) {
                int col = n0 + warp_n * 64 + nf * 8 + t4 * 2;
                float2 bz = *reinterpret_cast<const float2*>(bias + col);
                float v0 = fmaxf(acc[mf][nf][h * 2 + 0] + bz.x, 0.f) * wv;
                float v1 = fmaxf(acc[mf][nf][h * 2 + 1] + bz.y, 0.f) * wv;
                __half h0 = __float2half_rn(v0);
                __half h1 = __float2half_rn(v1);
                uint32_t hp = ((uint32_t)__half_as_ushort(h1) << 16) |
                              (uint32_t)__half_as_ushort(h0);
                *reinterpret_cast<uint32_t*>(hz + rbase + col) = hp;
            }
        }
    }
}

// ===================== layer-2 GEMM (compacted A, scatter to partials) ============
__global__ __launch_bounds__(TPB, 1) void gemm2_kernel(
    const __half* __restrict__ h16,           // [NE][BB][HH]
    const __half* __restrict__ w2s,           // [NE][OO][2*HH]
    const int* __restrict__ list, const int* __restrict__ cnt,
    float* __restrict__ part) {               // [NE][BB][OO]
    int z = blockIdx.z;
    int m0 = blockIdx.y * 128;
    int cz = cnt[z];
    if (m0 >= cz) return;
    int n0 = blockIdx.x * 256;

    extern __shared__ __align__(1024) char smem[];
    uint32_t sbase = smem_u32(smem);
    int* silist = reinterpret_cast<int*>(smem + ILIST_OFF);
    int tid = threadIdx.x, lid = tid & 31, wid = tid >> 5;
    int warp_m = wid >> 2, warp_n = wid & 3;

    if (tid < 128) silist[tid] = list[(size_t)z * BB + m0 + tid];
    __syncthreads();

    const __half* abase = h16 + (size_t)z * BB * HH + (size_t)m0 * HH;
    const __half* wrow = w2s + (size_t)z * OO * (2 * HH) + (size_t)n0 * (2 * HH);
    const int NC = HH / 64;    // 64

    float acc[4][8][4];
#pragma unroll
    for (int a = 0; a < 4; a++)
#pragma unroll
        for (int b = 0; b < 8; b++)
#pragma unroll
            for (int c = 0; c < 4; c++) acc[a][b][c] = 0.f;

    auto issue = [&](int ci) {
        int s = ci & 1, kk = ci * 64;
        uint32_t sa = sbase + s * ST_SZ;
#pragma unroll
        for (int i = 0; i < 4; i++) {
            int u = tid + i * TPB;
            int r = u >> 3, seg = u & 7;
            uint32_t off = SWZ((uint32_t)(r * 128 + seg * 16));
            cp_async16(sa + off, abase + (size_t)r * HH + kk + seg * 8);
        }
        load_B(sbase, s, tid, wrow, 2 * HH, HH, kk);
        cp_commit();
    };

    issue(0);
    for (int ci = 0; ci < NC; ci++) {
        if (ci + 1 < NC) { issue(ci + 1); cp_wait<1>(); } else { cp_wait<0>(); }
        __syncthreads();
        compute_chunk(sbase, ci & 1, warp_m, warp_n, lid, acc);
        __syncthreads();
    }

    // epilogue: scatter rows to part[z][token], mask padded rows
    int g = lid >> 2, t4 = lid & 3;
    float* pz = part + (size_t)z * BB * OO;
#pragma unroll
    for (int mf = 0; mf < 4; mf++) {
#pragma unroll
        for (int h = 0; h < 2; h++) {
            int row_l = warp_m * 64 + mf * 16 + g + h * 8;
            if (m0 + row_l < cz) {
                int tok = silist[row_l];
                size_t rbase = (size_t)tok * OO;
#pragma unroll
                for (int nf = 0; nf < 8; nf++) {
                    int col = n0 + warp_n * 64 + nf * 8 + t4 * 2;
                    float2 o;
                    o.x = acc[mf][nf][h * 2 + 0];
                    o.y = acc[mf][nf][h * 2 + 1];
                    *reinterpret_cast<float2*>(pz + rbase + col) = o;
                }
            }
        }
    }
}

// ===================== reduce: out = sum_active part[z] + sum_z gw*b2 ==============
__global__ void reduce_kernel(const float* __restrict__ part, const float* __restrict__ b2,
                              const float* __restrict__ gw, float* __restrict__ out) {
    const size_t n4 = (size_t)BB * OO / 4;
    size_t i = (size_t)blockIdx.x * blockDim.x + threadIdx.x;
    if (i >= n4) return;
    size_t b = i / (OO / 4);
    int o4 = (int)(i - b * (OO / 4));
    float4 acc = make_float4(0.f, 0.f, 0.f, 0.f);
#pragma unroll
    for (int z = 0; z < NE; z++) {
        float wv = gw[b * NE + z];
        float4 bz = reinterpret_cast<const float4*>(b2)[(size_t)z * (OO / 4) + o4];
        acc.x += wv * bz.x; acc.y += wv * bz.y;
        acc.z += wv * bz.z; acc.w += wv * bz.w;
        if (wv > 0.f) {
            float4 p = reinterpret_cast<const float4*>(part)[(size_t)z * n4 + i];
            acc.x += p.x; acc.y += p.y; acc.z += p.z; acc.w += p.w;
        }
    }
    reinterpret_cast<float4*>(out)[i] = acc;
}

// ---------------- host launcher ----------------
extern "C" void kernel_launch(void* const* d_in, const int* in_sizes, int n_in,
                              void* d_out, int out_size) {
    const float* x  = (const float*)d_in[0];
    const float* W1 = (const float*)d_in[1];
    const float* b1 = (const float*)d_in[2];
    const float* W2 = (const float*)d_in[3];
    const float* b2 = (const float*)d_in[4];
    const float* Wg = (const float*)d_in[5];
    const float* bg = (const float*)d_in[6];
    float* out = (float*)d_out;

    void *px16, *pw1s, *pw2s, *ph16, *pgw, *ppart, *plist, *pcnt;
    cudaGetSymbolAddress(&px16, g_x16);
    cudaGetSymbolAddress(&pw1s, g_w1s);
    cudaGetSymbolAddress(&pw2s, g_w2s);
    cudaGetSymbolAddress(&ph16, g_h16);
    cudaGetSymbolAddress(&pgw, g_gw);
    cudaGetSymbolAddress(&ppart, g_part);
    cudaGetSymbolAddress(&plist, g_list);
    cudaGetSymbolAddress(&pcnt, g_cnt);

    cudaFuncSetAttribute(gemm1_kernel, cudaFuncAttributeMaxDynamicSharedMemorySize, SMEM_SZ);
    cudaFuncSetAttribute(gemm2_kernel, cudaFuncAttributeMaxDynamicSharedMemorySize, SMEM_SZ);

    gate_kernel<<<BB, 256>>>(x, Wg, bg, (float*)pgw);
    build_lists<<<NE, 256>>>((const float*)pgw, (int*)plist, (int*)pcnt);
    tohalf_kernel<<<2048, 256>>>(x, (__half*)px16, (size_t)BB * DD / 4);
    splitw_kernel<<<16384, 256>>>(W1, (__half*)pw1s, DD, (size_t)NE * HH * DD);
    splitw_kernel<<<16384, 256>>>(W2, (__half*)pw2s, HH, (size_t)NE * OO * HH);

    // layer 1: compacted tokens per expert
    gemm1_kernel<<<dim3(HH / 256, BB / 128, NE), TPB, SMEM_SZ>>>(
        (const __half*)px16, (const __half*)pw1s, b1, (const float*)pgw,
        (const int*)plist, (const int*)pcnt, (__half*)ph16);

    // layer 2: compacted rows, scatter into per-expert partials
    gemm2_kernel<<<dim3(OO / 256, BB / 128, NE), TPB, SMEM_SZ>>>(
        (const __half*)ph16, (const __half*)pw2s,
        (const int*)plist, (const int*)pcnt, (float*)ppart);

    reduce_kernel<<<(BB * OO / 4 + 255) / 256, 256>>>(
        (const float*)ppart, b2, (const float*)pgw, out);
}

// round 6
// speedup vs baseline: 4.2335x; 1.6844x over previous
#include <cuda_runtime.h>
#include <cuda_fp16.h>
#include <cstdint>
#include <cstddef>

// ---------------- problem dims ----------------
#define BB 4096
#define DD 1024
#define HH 4096
#define OO 1024
#define NE 8
#define NAE 5

// ---------------- device scratch ----------------
__device__ __half g_x16[(size_t)BB * DD];                 // x rounded to fp16
__device__ __half g_w1h[(size_t)NE * HH * DD];            // W1 fp16
__device__ __half g_w2h[(size_t)NE * OO * HH];            // W2 fp16
__device__ __half g_h16[(size_t)NE * BB * HH];            // compacted gw-scaled h (fp16)
__device__ float g_part[(size_t)NE * BB * OO];            // per-expert layer-2 partials
__device__ float g_gw[(size_t)BB * NE];
__device__ int g_list[(size_t)NE * BB];
__device__ int g_cnt[NE];

// ---------------- helpers ----------------
__device__ __forceinline__ uint32_t smem_u32(const void* p) {
    uint32_t a;
    asm("{ .reg .u64 t; cvta.to.shared.u64 t, %1; cvt.u32.u64 %0, t; }" : "=r"(a) : "l"(p));
    return a;
}
#define SWZ(off) ((off) ^ (((off) >> 3) & 0x70))

__device__ __forceinline__ void cp_async16(uint32_t saddr, const void* gptr) {
    asm volatile("cp.async.cg.shared.global [%0], [%1], 16;\n" :: "r"(saddr), "l"(gptr));
}
__device__ __forceinline__ void cp_commit() {
    asm volatile("cp.async.commit_group;\n" ::: "memory");
}
template <int N>
__device__ __forceinline__ void cp_wait() {
    asm volatile("cp.async.wait_group %0;\n" :: "n"(N) : "memory");
}
__device__ __forceinline__ void ldsm_x4(uint32_t& r0, uint32_t& r1, uint32_t& r2,
                                        uint32_t& r3, uint32_t addr) {
    asm volatile("ldmatrix.sync.aligned.m8n8.x4.shared.b16 {%0,%1,%2,%3}, [%4];"
                 : "=r"(r0), "=r"(r1), "=r"(r2), "=r"(r3) : "r"(addr));
}
__device__ __forceinline__ void mma16816(float* c, const uint32_t* a, const uint32_t* b) {
    asm volatile(
        "mma.sync.aligned.m16n8k16.row.col.f32.f16.f16.f32 "
        "{%0,%1,%2,%3}, {%4,%5,%6,%7}, {%8,%9}, {%0,%1,%2,%3};"
        : "+f"(c[0]), "+f"(c[1]), "+f"(c[2]), "+f"(c[3])
        : "r"(a[0]), "r"(a[1]), "r"(a[2]), "r"(a[3]), "r"(b[0]), "r"(b[1]));
}

// ---------------- gate kernel (fp32, exact semantics) ----------------
__global__ void gate_kernel(const float* __restrict__ x, const float* __restrict__ Wg,
                            const float* __restrict__ bg, float* __restrict__ gw) {
    __shared__ float slog[NE];
    int b = blockIdx.x;
    int wid = threadIdx.x >> 5, lid = threadIdx.x & 31;
    const float* xr = x + (size_t)b * DD;
    const float* wr = Wg + (size_t)wid * DD;
    float s = 0.f;
    for (int i = lid; i < DD; i += 32) s += xr[i] * wr[i];
#pragma unroll
    for (int o = 16; o > 0; o >>= 1) s += __shfl_xor_sync(0xffffffffu, s, o);
    if (lid == 0) slog[wid] = s + bg[wid];
    __syncthreads();
    if (threadIdx.x == 0) {
        const float invT = 0.36787944117144233f;
        float l[NE], mx = -1e30f;
#pragma unroll
        for (int i = 0; i < NE; i++) { l[i] = slog[i] * invT; mx = fmaxf(mx, l[i]); }
        float p[NE], se = 0.f;
#pragma unroll
        for (int i = 0; i < NE; i++) { p[i] = expf(l[i] - mx); se += p[i]; }
        float inv_se = 1.f / se;
#pragma unroll
        for (int i = 0; i < NE; i++) p[i] *= inv_se;
        bool sel[NE];
#pragma unroll
        for (int i = 0; i < NE; i++) sel[i] = false;
        float ss = 0.f;
        for (int it = 0; it < NAE; it++) {
            int bi = 0; float bv = -1.f;
#pragma unroll
            for (int i = 0; i < NE; i++)
                if (!sel[i] && p[i] > bv) { bv = p[i]; bi = i; }
            sel[bi] = true; ss += bv;
        }
        float inv = 1.f / (ss + 1e-8f);
#pragma unroll
        for (int i = 0; i < NE; i++)
            gw[(size_t)b * NE + i] = sel[i] ? p[i] * inv : 0.f;
    }
}

// ---------------- per-expert token list (deterministic, token order) ----------------
__global__ void build_lists(const float* __restrict__ gw, int* __restrict__ list,
                            int* __restrict__ cnt) {
    int z = blockIdx.x, tid = threadIdx.x;
    __shared__ int sbase;
    __shared__ int wtot[8];
    if (tid == 0) sbase = 0;
    __syncthreads();
    for (int t0 = 0; t0 < BB; t0 += 256) {
        int b = t0 + tid;
        int act = gw[(size_t)b * NE + z] > 0.f;
        unsigned m = __ballot_sync(0xffffffffu, act);
        int wid = tid >> 5, lid = tid & 31;
        int wpre = __popc(m & ((1u << lid) - 1u));
        if (lid == 31) wtot[wid] = __popc(m);
        __syncthreads();
        int woff = 0;
        for (int w = 0; w < wid; w++) woff += wtot[w];
        if (act) list[(size_t)z * BB + sbase + woff + wpre] = b;
        __syncthreads();
        if (tid == 0) {
            int tot = 0;
            for (int w = 0; w < 8; w++) tot += wtot[w];
            sbase += tot;
        }
        __syncthreads();
    }
    int c = sbase;
    if (tid == 0) cnt[z] = c;
    int cpad = (c + 127) & ~127;
    for (int i = c + tid; i < cpad; i += 256) list[(size_t)z * BB + i] = 0;
}

// ---------------- fp32 -> fp16 round ----------------
__global__ void tohalf_kernel(const float* __restrict__ in, __half* __restrict__ out,
                              size_t n4) {
    size_t i = (size_t)blockIdx.x * blockDim.x + threadIdx.x;
    size_t str = (size_t)gridDim.x * blockDim.x;
    for (; i < n4; i += str) {
        float4 v = reinterpret_cast<const float4*>(in)[i];
        __half h[4] = {__float2half_rn(v.x), __float2half_rn(v.y),
                       __float2half_rn(v.z), __float2half_rn(v.w)};
        *reinterpret_cast<uint2*>(out + i * 4) = *reinterpret_cast<uint2*>(h);
    }
}

// ---------------- GEMM config: 128x256 tile, BK=64, single-term fp16 ----------------
#define TPB 256
#define ST_SZ 49152            // A 16K + B 32K
#define B_OFF 16384
#define ILIST_OFF (2 * ST_SZ)  // 98304
#define SMEM_SZ (2 * ST_SZ + 512)

// compute one BK=64 chunk: acc += A x B
__device__ __forceinline__ void compute_chunk(uint32_t sbase, int s, int warp_m,
                                              int warp_n, int lid, float acc[4][8][4]) {
    uint32_t aB = sbase + s * ST_SZ;
    uint32_t bB = aB + B_OFF;
    int rA = warp_m * 64 + (lid & 15);
    int rB = warp_n * 64 + (lid & 15);
    int kh = (lid >> 4) * 16;
#pragma unroll
    for (int ks = 0; ks < 4; ks++) {
        int colb = ks * 32 + kh;
        uint32_t a[4][4];
#pragma unroll
        for (int mf = 0; mf < 4; mf++)
            ldsm_x4(a[mf][0], a[mf][1], a[mf][2], a[mf][3],
                    aB + SWZ((uint32_t)((rA + mf * 16) * 128 + colb)));
        uint32_t bh[8][2];
#pragma unroll
        for (int pr = 0; pr < 4; pr++) {
            uint32_t r0, r1, r2, r3;
            ldsm_x4(r0, r1, r2, r3, bB + SWZ((uint32_t)((rB + pr * 16) * 128 + colb)));
            bh[pr * 2 + 0][0] = r0; bh[pr * 2 + 1][0] = r1;
            bh[pr * 2 + 0][1] = r2; bh[pr * 2 + 1][1] = r3;
        }
#pragma unroll
        for (int mf = 0; mf < 4; mf++)
#pragma unroll
            for (int nf = 0; nf < 8; nf++)
                mma16816(acc[mf][nf], a[mf], bh[nf]);
    }
}

// B loader: 256 rows x 64 cols fp16 from row-major [ldB]
__device__ __forceinline__ void load_B(uint32_t sbase, int s, int tid,
                                       const __half* __restrict__ wrow, int ldB, int kk) {
    uint32_t sb = sbase + s * ST_SZ + B_OFF;
#pragma unroll
    for (int i = 0; i < 8; i++) {
        int u = tid + i * TPB;
        int r = u >> 3, seg = u & 7;
        uint32_t off = SWZ((uint32_t)(r * 128 + seg * 16));
        cp_async16(sb + off, wrow + (size_t)r * ldB + kk + seg * 8);
    }
}

// ===================== layer-1 GEMM (gathered A) =====================
__global__ __launch_bounds__(TPB, 1) void gemm1_kernel(
    const __half* __restrict__ x16,           // [BB][DD]
    const __half* __restrict__ w1h,           // [NE][HH][DD]
    const float* __restrict__ b1,             // [NE][HH]
    const float* __restrict__ gw,             // [BB][NE]
    const int* __restrict__ list, const int* __restrict__ cnt,
    __half* __restrict__ h16) {               // [NE][BB][HH] (compacted rows)
    int z = blockIdx.z;
    int m0 = blockIdx.y * 128;
    int cz = cnt[z];
    if (m0 >= cz) return;
    int n0 = blockIdx.x * 256;

    extern __shared__ __align__(1024) char smem[];
    uint32_t sbase = smem_u32(smem);
    int* silist = reinterpret_cast<int*>(smem + ILIST_OFF);
    int tid = threadIdx.x, lid = tid & 31, wid = tid >> 5;
    int warp_m = wid >> 2, warp_n = wid & 3;

    if (tid < 128) silist[tid] = list[(size_t)z * BB + m0 + tid];
    __syncthreads();

    const __half* wrow = w1h + (size_t)z * HH * DD + (size_t)n0 * DD;
    const int NC = DD / 64;    // 16

    float acc[4][8][4];
#pragma unroll
    for (int a = 0; a < 4; a++)
#pragma unroll
        for (int b = 0; b < 8; b++)
#pragma unroll
            for (int c = 0; c < 4; c++) acc[a][b][c] = 0.f;

    auto issue = [&](int ci) {
        int s = ci & 1, kk = ci * 64;
        uint32_t sa = sbase + s * ST_SZ;
#pragma unroll
        for (int i = 0; i < 4; i++) {
            int u = tid + i * TPB;
            int r = u >> 3, seg = u & 7;
            int tok = silist[r];
            uint32_t off = SWZ((uint32_t)(r * 128 + seg * 16));
            cp_async16(sa + off, x16 + (size_t)tok * DD + kk + seg * 8);
        }
        load_B(sbase, s, tid, wrow, DD, kk);
        cp_commit();
    };

    issue(0);
    for (int ci = 0; ci < NC; ci++) {
        if (ci + 1 < NC) { issue(ci + 1); cp_wait<1>(); } else { cp_wait<0>(); }
        __syncthreads();
        compute_chunk(sbase, ci & 1, warp_m, warp_n, lid, acc);
        __syncthreads();
    }

    // epilogue: bias + relu, gw-scale, round to fp16 -> h16[z][m0+row][col]
    int g = lid >> 2, t4 = lid & 3;
    const float* bias = b1 + (size_t)z * HH;
    __half* hz = h16 + (size_t)z * BB * HH;
#pragma unroll
    for (int mf = 0; mf < 4; mf++) {
#pragma unroll
        for (int h = 0; h < 2; h++) {
            int row_l = warp_m * 64 + mf * 16 + g + h * 8;
            int tok = silist[row_l];
            float wv = gw[(size_t)tok * NE + z];
            size_t rbase = (size_t)(m0 + row_l) * HH;
#pragma unroll
            for (int nf = 0; nf < 8; nf++) {
                int col = n0 + warp_n * 64 + nf * 8 + t4 * 2;
                float2 bz = *reinterpret_cast<const float2*>(bias + col);
                float v0 = fmaxf(acc[mf][nf][h * 2 + 0] + bz.x, 0.f) * wv;
                float v1 = fmaxf(acc[mf][nf][h * 2 + 1] + bz.y, 0.f) * wv;
                __half h0 = __float2half_rn(v0);
                __half h1 = __float2half_rn(v1);
                uint32_t hp = ((uint32_t)__half_as_ushort(h1) << 16) |
                              (uint32_t)__half_as_ushort(h0);
                *reinterpret_cast<uint32_t*>(hz + rbase + col) = hp;
            }
        }
    }
}

// ===================== layer-2 GEMM (compacted A, scatter to partials) ============
__global__ __launch_bounds__(TPB, 1) void gemm2_kernel(
    const __half* __restrict__ h16,           // [NE][BB][HH]
    const __half* __restrict__ w2h,           // [NE][OO][HH]
    const int* __restrict__ list, const int* __restrict__ cnt,
    float* __restrict__ part) {               // [NE][BB][OO]
    int z = blockIdx.z;
    int m0 = blockIdx.y * 128;
    int cz = cnt[z];
    if (m0 >= cz) return;
    int n0 = blockIdx.x * 256;

    extern __shared__ __align__(1024) char smem[];
    uint32_t sbase = smem_u32(smem);
    int* silist = reinterpret_cast<int*>(smem + ILIST_OFF);
    int tid = threadIdx.x, lid = tid & 31, wid = tid >> 5;
    int warp_m = wid >> 2, warp_n = wid & 3;

    if (tid < 128) silist[tid] = list[(size_t)z * BB + m0 + tid];
    __syncthreads();

    const __half* abase = h16 + (size_t)z * BB * HH + (size_t)m0 * HH;
    const __half* wrow = w2h + (size_t)z * OO * HH + (size_t)n0 * HH;
    const int NC = HH / 64;    // 64

    float acc[4][8][4];
#pragma unroll
    for (int a = 0; a < 4; a++)
#pragma unroll
        for (int b = 0; b < 8; b++)
#pragma unroll
            for (int c = 0; c < 4; c++) acc[a][b][c] = 0.f;

    auto issue = [&](int ci) {
        int s = ci & 1, kk = ci * 64;
        uint32_t sa = sbase + s * ST_SZ;
#pragma unroll
        for (int i = 0; i < 4; i++) {
            int u = tid + i * TPB;
            int r = u >> 3, seg = u & 7;
            uint32_t off = SWZ((uint32_t)(r * 128 + seg * 16));
            cp_async16(sa + off, abase + (size_t)r * HH + kk + seg * 8);
        }
        load_B(sbase, s, tid, wrow, HH, kk);
        cp_commit();
    };

    issue(0);
    for (int ci = 0; ci < NC; ci++) {
        if (ci + 1 < NC) { issue(ci + 1); cp_wait<1>(); } else { cp_wait<0>(); }
        __syncthreads();
        compute_chunk(sbase, ci & 1, warp_m, warp_n, lid, acc);
        __syncthreads();
    }

    // epilogue: scatter rows to part[z][token], mask padded rows
    int g = lid >> 2, t4 = lid & 3;
    float* pz = part + (size_t)z * BB * OO;
#pragma unroll
    for (int mf = 0; mf < 4; mf++) {
#pragma unroll
        for (int h = 0; h < 2; h++) {
            int row_l = warp_m * 64 + mf * 16 + g + h * 8;
            if (m0 + row_l < cz) {
                int tok = silist[row_l];
                size_t rbase = (size_t)tok * OO;
#pragma unroll
                for (int nf = 0; nf < 8; nf++) {
                    int col = n0 + warp_n * 64 + nf * 8 + t4 * 2;
                    float2 o;
                    o.x = acc[mf][nf][h * 2 + 0];
                    o.y = acc[mf][nf][h * 2 + 1];
                    *reinterpret_cast<float2*>(pz + rbase + col) = o;
                }
            }
        }
    }
}

// ===================== reduce: out = sum_active part[z] + sum_z gw*b2 ==============
__global__ void reduce_kernel(const float* __restrict__ part, const float* __restrict__ b2,
                              const float* __restrict__ gw, float* __restrict__ out) {
    const size_t n4 = (size_t)BB * OO / 4;
    size_t i = (size_t)blockIdx.x * blockDim.x + threadIdx.x;
    if (i >= n4) return;
    size_t b = i / (OO / 4);
    int o4 = (int)(i - b * (OO / 4));
    float4 acc = make_float4(0.f, 0.f, 0.f, 0.f);
#pragma unroll
    for (int z = 0; z < NE; z++) {
        float wv = gw[b * NE + z];
        float4 bz = reinterpret_cast<const float4*>(b2)[(size_t)z * (OO / 4) + o4];
        acc.x += wv * bz.x; acc.y += wv * bz.y;
        acc.z += wv * bz.z; acc.w += wv * bz.w;
        if (wv > 0.f) {
            float4 p = reinterpret_cast<const float4*>(part)[(size_t)z * n4 + i];
            acc.x += p.x; acc.y += p.y; acc.z += p.z; acc.w += p.w;
        }
    }
    reinterpret_cast<float4*>(out)[i] = acc;
}

// ---------------- host launcher ----------------
extern "C" void kernel_launch(void* const* d_in, const int* in_sizes, int n_in,
                              void* d_out, int out_size) {
    const float* x  = (const float*)d_in[0];
    const float* W1 = (const float*)d_in[1];
    const float* b1 = (const float*)d_in[2];
    const float* W2 = (const float*)d_in[3];
    const float* b2 = (const float*)d_in[4];
    const float* Wg = (const float*)d_in[5];
    const float* bg = (const float*)d_in[6];
    float* out = (float*)d_out;

    void *px16, *pw1h, *pw2h, *ph16, *pgw, *ppart, *plist, *pcnt;
    cudaGetSymbolAddress(&px16, g_x16);
    cudaGetSymbolAddress(&pw1h, g_w1h);
    cudaGetSymbolAddress(&pw2h, g_w2h);
    cudaGetSymbolAddress(&ph16, g_h16);
    cudaGetSymbolAddress(&pgw, g_gw);
    cudaGetSymbolAddress(&ppart, g_part);
    cudaGetSymbolAddress(&plist, g_list);
    cudaGetSymbolAddress(&pcnt, g_cnt);

    cudaFuncSetAttribute(gemm1_kernel, cudaFuncAttributeMaxDynamicSharedMemorySize, SMEM_SZ);
    cudaFuncSetAttribute(gemm2_kernel, cudaFuncAttributeMaxDynamicSharedMemorySize, SMEM_SZ);

    gate_kernel<<<BB, 256>>>(x, Wg, bg, (float*)pgw);
    build_lists<<<NE, 256>>>((const float*)pgw, (int*)plist, (int*)pcnt);
    tohalf_kernel<<<2048, 256>>>(x, (__half*)px16, (size_t)BB * DD / 4);
    tohalf_kernel<<<16384, 256>>>(W1, (__half*)pw1h, (size_t)NE * HH * DD / 4);
    tohalf_kernel<<<16384, 256>>>(W2, (__half*)pw2h, (size_t)NE * OO * HH / 4);

    // layer 1: compacted tokens per expert
    gemm1_kernel<<<dim3(HH / 256, BB / 128, NE), TPB, SMEM_SZ>>>(
        (const __half*)px16, (const __half*)pw1h, b1, (const float*)pgw,
        (const int*)plist, (const int*)pcnt, (__half*)ph16);

    // layer 2: compacted rows, scatter into per-expert partials
    gemm2_kernel<<<dim3(OO / 256, BB / 128, NE), TPB, SMEM_SZ>>>(
        (const __half*)ph16, (const __half*)pw2h,
        (const int*)plist, (const int*)pcnt, (float*)ppart);

    reduce_kernel<<<(BB * OO / 4 + 255) / 256, 256>>>(
        (const float*)ppart, b2, (const float*)pgw, out);
}

// round 7
// speedup vs baseline: 4.3734x; 1.0330x over previous
#include <cuda_runtime.h>
#include <cuda_fp16.h>
#include <cstdint>
#include <cstddef>

// ---------------- problem dims ----------------
#define BB 4096
#define DD 1024
#define HH 4096
#define OO 1024
#define NE 8
#define NAE 5

// ---------------- device scratch ----------------
__device__ __half g_x16[(size_t)BB * DD];                 // x rounded to fp16
__device__ __half g_w1h[(size_t)NE * HH * DD];            // W1 fp16
__device__ __half g_w2h[(size_t)NE * OO * HH];            // W2 fp16
__device__ __half g_h16[(size_t)NE * BB * HH];            // compacted gw-scaled h (fp16)
__device__ __half g_part[(size_t)2 * NE * BB * OO];       // layer-2 split-K fp16 partials
__device__ float g_gw[(size_t)BB * NE];
__device__ int g_list[(size_t)NE * BB];
__device__ int g_cnt[NE];

// ---------------- helpers ----------------
__device__ __forceinline__ uint32_t smem_u32(const void* p) {
    uint32_t a;
    asm("{ .reg .u64 t; cvta.to.shared.u64 t, %1; cvt.u32.u64 %0, t; }" : "=r"(a) : "l"(p));
    return a;
}
#define SWZ(off) ((off) ^ (((off) >> 3) & 0x70))

__device__ __forceinline__ void cp_async16(uint32_t saddr, const void* gptr) {
    asm volatile("cp.async.cg.shared.global [%0], [%1], 16;\n" :: "r"(saddr), "l"(gptr));
}
__device__ __forceinline__ void cp_commit() {
    asm volatile("cp.async.commit_group;\n" ::: "memory");
}
template <int N>
__device__ __forceinline__ void cp_wait() {
    asm volatile("cp.async.wait_group %0;\n" :: "n"(N) : "memory");
}
__device__ __forceinline__ void ldsm_x4(uint32_t& r0, uint32_t& r1, uint32_t& r2,
                                        uint32_t& r3, uint32_t addr) {
    asm volatile("ldmatrix.sync.aligned.m8n8.x4.shared.b16 {%0,%1,%2,%3}, [%4];"
                 : "=r"(r0), "=r"(r1), "=r"(r2), "=r"(r3) : "r"(addr));
}
__device__ __forceinline__ void mma16816(float* c, const uint32_t* a, const uint32_t* b) {
    asm volatile(
        "mma.sync.aligned.m16n8k16.row.col.f32.f16.f16.f32 "
        "{%0,%1,%2,%3}, {%4,%5,%6,%7}, {%8,%9}, {%0,%1,%2,%3};"
        : "+f"(c[0]), "+f"(c[1]), "+f"(c[2]), "+f"(c[3])
        : "r"(a[0]), "r"(a[1]), "r"(a[2]), "r"(a[3]), "r"(b[0]), "r"(b[1]));
}

// ---------------- gate kernel (fp32, exact semantics) ----------------
__global__ void gate_kernel(const float* __restrict__ x, const float* __restrict__ Wg,
                            const float* __restrict__ bg, float* __restrict__ gw) {
    __shared__ float slog[NE];
    int b = blockIdx.x;
    int wid = threadIdx.x >> 5, lid = threadIdx.x & 31;
    const float* xr = x + (size_t)b * DD;
    const float* wr = Wg + (size_t)wid * DD;
    float s = 0.f;
    for (int i = lid; i < DD; i += 32) s += xr[i] * wr[i];
#pragma unroll
    for (int o = 16; o > 0; o >>= 1) s += __shfl_xor_sync(0xffffffffu, s, o);
    if (lid == 0) slog[wid] = s + bg[wid];
    __syncthreads();
    if (threadIdx.x == 0) {
        const float invT = 0.36787944117144233f;
        float l[NE], mx = -1e30f;
#pragma unroll
        for (int i = 0; i < NE; i++) { l[i] = slog[i] * invT; mx = fmaxf(mx, l[i]); }
        float p[NE], se = 0.f;
#pragma unroll
        for (int i = 0; i < NE; i++) { p[i] = expf(l[i] - mx); se += p[i]; }
        float inv_se = 1.f / se;
#pragma unroll
        for (int i = 0; i < NE; i++) p[i] *= inv_se;
        bool sel[NE];
#pragma unroll
        for (int i = 0; i < NE; i++) sel[i] = false;
        float ss = 0.f;
        for (int it = 0; it < NAE; it++) {
            int bi = 0; float bv = -1.f;
#pragma unroll
            for (int i = 0; i < NE; i++)
                if (!sel[i] && p[i] > bv) { bv = p[i]; bi = i; }
            sel[bi] = true; ss += bv;
        }
        float inv = 1.f / (ss + 1e-8f);
#pragma unroll
        for (int i = 0; i < NE; i++)
            gw[(size_t)b * NE + i] = sel[i] ? p[i] * inv : 0.f;
    }
}

// ---------------- per-expert token list (deterministic, token order) ----------------
__global__ void build_lists(const float* __restrict__ gw, int* __restrict__ list,
                            int* __restrict__ cnt) {
    int z = blockIdx.x, tid = threadIdx.x;
    __shared__ int sbase;
    __shared__ int wtot[8];
    if (tid == 0) sbase = 0;
    __syncthreads();
    for (int t0 = 0; t0 < BB; t0 += 256) {
        int b = t0 + tid;
        int act = gw[(size_t)b * NE + z] > 0.f;
        unsigned m = __ballot_sync(0xffffffffu, act);
        int wid = tid >> 5, lid = tid & 31;
        int wpre = __popc(m & ((1u << lid) - 1u));
        if (lid == 31) wtot[wid] = __popc(m);
        __syncthreads();
        int woff = 0;
        for (int w = 0; w < wid; w++) woff += wtot[w];
        if (act) list[(size_t)z * BB + sbase + woff + wpre] = b;
        __syncthreads();
        if (tid == 0) {
            int tot = 0;
            for (int w = 0; w < 8; w++) tot += wtot[w];
            sbase += tot;
        }
        __syncthreads();
    }
    int c = sbase;
    if (tid == 0) cnt[z] = c;
    int cpad = (c + 127) & ~127;
    for (int i = c + tid; i < cpad; i += 256) list[(size_t)z * BB + i] = 0;
}

// ---------------- fp32 -> fp16 round ----------------
__global__ void tohalf_kernel(const float* __restrict__ in, __half* __restrict__ out,
                              size_t n4) {
    size_t i = (size_t)blockIdx.x * blockDim.x + threadIdx.x;
    size_t str = (size_t)gridDim.x * blockDim.x;
    for (; i < n4; i += str) {
        float4 v = reinterpret_cast<const float4*>(in)[i];
        __half h[4] = {__float2half_rn(v.x), __float2half_rn(v.y),
                       __float2half_rn(v.z), __float2half_rn(v.w)};
        *reinterpret_cast<uint2*>(out + i * 4) = *reinterpret_cast<uint2*>(h);
    }
}

// ---------------- GEMM config: 128x256 tile, BK=64, single-term fp16 ----------------
#define TPB 256
#define ST_SZ 49152            // A 16K + B 32K
#define B_OFF 16384
#define ILIST_OFF (2 * ST_SZ)  // 98304
#define SMEM_SZ (2 * ST_SZ + 512)

// compute one BK=64 chunk: acc += A x B
__device__ __forceinline__ void compute_chunk(uint32_t sbase, int s, int warp_m,
                                              int warp_n, int lid, float acc[4][8][4]) {
    uint32_t aB = sbase + s * ST_SZ;
    uint32_t bB = aB + B_OFF;
    int rA = warp_m * 64 + (lid & 15);
    int rB = warp_n * 64 + (lid & 15);
    int kh = (lid >> 4) * 16;
#pragma unroll
    for (int ks = 0; ks < 4; ks++) {
        int colb = ks * 32 + kh;
        uint32_t a[4][4];
#pragma unroll
        for (int mf = 0; mf < 4; mf++)
            ldsm_x4(a[mf][0], a[mf][1], a[mf][2], a[mf][3],
                    aB + SWZ((uint32_t)((rA + mf * 16) * 128 + colb)));
        uint32_t bh[8][2];
#pragma unroll
        for (int pr = 0; pr < 4; pr++) {
            uint32_t r0, r1, r2, r3;
            ldsm_x4(r0, r1, r2, r3, bB + SWZ((uint32_t)((rB + pr * 16) * 128 + colb)));
            bh[pr * 2 + 0][0] = r0; bh[pr * 2 + 1][0] = r1;
            bh[pr * 2 + 0][1] = r2; bh[pr * 2 + 1][1] = r3;
        }
#pragma unroll
        for (int mf = 0; mf < 4; mf++)
#pragma unroll
            for (int nf = 0; nf < 8; nf++)
                mma16816(acc[mf][nf], a[mf], bh[nf]);
    }
}

// B loader: 256 rows x 64 cols fp16 from row-major [ldB]
__device__ __forceinline__ void load_B(uint32_t sbase, int s, int tid,
                                       const __half* __restrict__ wrow, int ldB, int kk) {
    uint32_t sb = sbase + s * ST_SZ + B_OFF;
#pragma unroll
    for (int i = 0; i < 8; i++) {
        int u = tid + i * TPB;
        int r = u >> 3, seg = u & 7;
        uint32_t off = SWZ((uint32_t)(r * 128 + seg * 16));
        cp_async16(sb + off, wrow + (size_t)r * ldB + kk + seg * 8);
    }
}

// ===================== layer-1 GEMM (gathered A) =====================
__global__ __launch_bounds__(TPB, 1) void gemm1_kernel(
    const __half* __restrict__ x16,           // [BB][DD]
    const __half* __restrict__ w1h,           // [NE][HH][DD]
    const float* __restrict__ b1,             // [NE][HH]
    const float* __restrict__ gw,             // [BB][NE]
    const int* __restrict__ list, const int* __restrict__ cnt,
    __half* __restrict__ h16) {               // [NE][BB][HH] (compacted rows)
    int z = blockIdx.z;
    int m0 = blockIdx.y * 128;
    int cz = cnt[z];
    if (m0 >= cz) return;
    int n0 = blockIdx.x * 256;

    extern __shared__ __align__(1024) char smem[];
    uint32_t sbase = smem_u32(smem);
    int* silist = reinterpret_cast<int*>(smem + ILIST_OFF);
    int tid = threadIdx.x, lid = tid & 31, wid = tid >> 5;
    int warp_m = wid >> 2, warp_n = wid & 3;

    if (tid < 128) silist[tid] = list[(size_t)z * BB + m0 + tid];
    __syncthreads();

    const __half* wrow = w1h + (size_t)z * HH * DD + (size_t)n0 * DD;
    const int NC = DD / 64;    // 16

    float acc[4][8][4];
#pragma unroll
    for (int a = 0; a < 4; a++)
#pragma unroll
        for (int b = 0; b < 8; b++)
#pragma unroll
            for (int c = 0; c < 4; c++) acc[a][b][c] = 0.f;

    auto issue = [&](int ci) {
        int s = ci & 1, kk = ci * 64;
        uint32_t sa = sbase + s * ST_SZ;
#pragma unroll
        for (int i = 0; i < 4; i++) {
            int u = tid + i * TPB;
            int r = u >> 3, seg = u & 7;
            int tok = silist[r];
            uint32_t off = SWZ((uint32_t)(r * 128 + seg * 16));
            cp_async16(sa + off, x16 + (size_t)tok * DD + kk + seg * 8);
        }
        load_B(sbase, s, tid, wrow, DD, kk);
        cp_commit();
    };

    issue(0);
    for (int ci = 0; ci < NC; ci++) {
        if (ci + 1 < NC) { issue(ci + 1); cp_wait<1>(); } else { cp_wait<0>(); }
        __syncthreads();
        compute_chunk(sbase, ci & 1, warp_m, warp_n, lid, acc);
        __syncthreads();
    }

    // epilogue: bias + relu, gw-scale, round to fp16 -> h16[z][m0+row][col]
    int g = lid >> 2, t4 = lid & 3;
    const float* bias = b1 + (size_t)z * HH;
    __half* hz = h16 + (size_t)z * BB * HH;
#pragma unroll
    for (int mf = 0; mf < 4; mf++) {
#pragma unroll
        for (int h = 0; h < 2; h++) {
            int row_l = warp_m * 64 + mf * 16 + g + h * 8;
            int tok = silist[row_l];
            float wv = gw[(size_t)tok * NE + z];
            size_t rbase = (size_t)(m0 + row_l) * HH;
#pragma unroll
            for (int nf = 0; nf < 8; nf++) {
                int col = n0 + warp_n * 64 + nf * 8 + t4 * 2;
                float2 bz = *reinterpret_cast<const float2*>(bias + col);
                float v0 = fmaxf(acc[mf][nf][h * 2 + 0] + bz.x, 0.f) * wv;
                float v1 = fmaxf(acc[mf][nf][h * 2 + 1] + bz.y, 0.f) * wv;
                __half h0 = __float2half_rn(v0);
                __half h1 = __float2half_rn(v1);
                uint32_t hp = ((uint32_t)__half_as_ushort(h1) << 16) |
                              (uint32_t)__half_as_ushort(h0);
                *reinterpret_cast<uint32_t*>(hz + rbase + col) = hp;
            }
        }
    }
}

// ===================== layer-2 GEMM (compacted A, split-K=2, fp16 partials) ========
__global__ __launch_bounds__(TPB, 1) void gemm2_kernel(
    const __half* __restrict__ h16,           // [NE][BB][HH]
    const __half* __restrict__ w2h,           // [NE][OO][HH]
    const int* __restrict__ list, const int* __restrict__ cnt,
    __half* __restrict__ part) {              // [2][NE][BB][OO] fp16
    int zz = blockIdx.z;
    int z = zz & 7;
    int khalf = zz >> 3;                      // 0 or 1
    int m0 = blockIdx.y * 128;
    int cz = cnt[z];
    if (m0 >= cz) return;
    int n0 = blockIdx.x * 256;

    extern __shared__ __align__(1024) char smem[];
    uint32_t sbase = smem_u32(smem);
    int* silist = reinterpret_cast<int*>(smem + ILIST_OFF);
    int tid = threadIdx.x, lid = tid & 31, wid = tid >> 5;
    int warp_m = wid >> 2, warp_n = wid & 3;

    if (tid < 128) silist[tid] = list[(size_t)z * BB + m0 + tid];
    __syncthreads();

    const __half* abase = h16 + (size_t)z * BB * HH + (size_t)m0 * HH + khalf * (HH / 2);
    const __half* wrow = w2h + (size_t)z * OO * HH + (size_t)n0 * HH + khalf * (HH / 2);
    const int NC = HH / 128;   // 32 chunks of 64 over half of H

    float acc[4][8][4];
#pragma unroll
    for (int a = 0; a < 4; a++)
#pragma unroll
        for (int b = 0; b < 8; b++)
#pragma unroll
            for (int c = 0; c < 4; c++) acc[a][b][c] = 0.f;

    auto issue = [&](int ci) {
        int s = ci & 1, kk = ci * 64;
        uint32_t sa = sbase + s * ST_SZ;
#pragma unroll
        for (int i = 0; i < 4; i++) {
            int u = tid + i * TPB;
            int r = u >> 3, seg = u & 7;
            uint32_t off = SWZ((uint32_t)(r * 128 + seg * 16));
            cp_async16(sa + off, abase + (size_t)r * HH + kk + seg * 8);
        }
        load_B(sbase, s, tid, wrow, HH, kk);
        cp_commit();
    };

    issue(0);
    for (int ci = 0; ci < NC; ci++) {
        if (ci + 1 < NC) { issue(ci + 1); cp_wait<1>(); } else { cp_wait<0>(); }
        __syncthreads();
        compute_chunk(sbase, ci & 1, warp_m, warp_n, lid, acc);
        __syncthreads();
    }

    // epilogue: scatter fp16 partial rows to part[khalf][z][token], mask padded rows
    int g = lid >> 2, t4 = lid & 3;
    __half* pz = part + ((size_t)khalf * NE + z) * BB * OO;
#pragma unroll
    for (int mf = 0; mf < 4; mf++) {
#pragma unroll
        for (int h = 0; h < 2; h++) {
            int row_l = warp_m * 64 + mf * 16 + g + h * 8;
            if (m0 + row_l < cz) {
                int tok = silist[row_l];
                size_t rbase = (size_t)tok * OO;
#pragma unroll
                for (int nf = 0; nf < 8; nf++) {
                    int col = n0 + warp_n * 64 + nf * 8 + t4 * 2;
                    __half p0 = __float2half_rn(acc[mf][nf][h * 2 + 0]);
                    __half p1 = __float2half_rn(acc[mf][nf][h * 2 + 1]);
                    uint32_t pp = ((uint32_t)__half_as_ushort(p1) << 16) |
                                  (uint32_t)__half_as_ushort(p0);
                    *reinterpret_cast<uint32_t*>(pz + rbase + col) = pp;
                }
            }
        }
    }
}

// ===================== reduce: out = sum halves/experts + sum_z gw*b2 ==============
__global__ void reduce_kernel(const __half* __restrict__ part, const float* __restrict__ b2,
                              const float* __restrict__ gw, float* __restrict__ out) {
    const size_t n4 = (size_t)BB * OO / 4;
    size_t i = (size_t)blockIdx.x * blockDim.x + threadIdx.x;
    if (i >= n4) return;
    size_t b = i / (OO / 4);
    int o4 = (int)(i - b * (OO / 4));
    float4 acc = make_float4(0.f, 0.f, 0.f, 0.f);
#pragma unroll
    for (int z = 0; z < NE; z++) {
        float wv = gw[b * NE + z];
        float4 bz = reinterpret_cast<const float4*>(b2)[(size_t)z * (OO / 4) + o4];
        acc.x += wv * bz.x; acc.y += wv * bz.y;
        acc.z += wv * bz.z; acc.w += wv * bz.w;
        if (wv > 0.f) {
            size_t base = ((size_t)z * BB * OO + b * OO + o4 * 4) / 4;  // in __half2 pairs? no:
            // element base:
            size_t ebase = (size_t)z * BB * OO + b * OO + (size_t)o4 * 4;
            const __half2* p0 = reinterpret_cast<const __half2*>(part + ebase);
            const __half2* p1 = reinterpret_cast<const __half2*>(part +
                                  (size_t)NE * BB * OO + ebase);
            float2 a0 = __half22float2(p0[0]);
            float2 a1 = __half22float2(p0[1]);
            float2 c0 = __half22float2(p1[0]);
            float2 c1 = __half22float2(p1[1]);
            acc.x += a0.x + c0.x; acc.y += a0.y + c0.y;
            acc.z += a1.x + c1.x; acc.w += a1.y + c1.y;
            (void)base;
        }
    }
    reinterpret_cast<float4*>(out)[i] = acc;
}

// ---------------- host launcher ----------------
extern "C" void kernel_launch(void* const* d_in, const int* in_sizes, int n_in,
                              void* d_out, int out_size) {
    const float* x  = (const float*)d_in[0];
    const float* W1 = (const float*)d_in[1];
    const float* b1 = (const float*)d_in[2];
    const float* W2 = (const float*)d_in[3];
    const float* b2 = (const float*)d_in[4];
    const float* Wg = (const float*)d_in[5];
    const float* bg = (const float*)d_in[6];
    float* out = (float*)d_out;

    void *px16, *pw1h, *pw2h, *ph16, *pgw, *ppart, *plist, *pcnt;
    cudaGetSymbolAddress(&px16, g_x16);
    cudaGetSymbolAddress(&pw1h, g_w1h);
    cudaGetSymbolAddress(&pw2h, g_w2h);
    cudaGetSymbolAddress(&ph16, g_h16);
    cudaGetSymbolAddress(&pgw, g_gw);
    cudaGetSymbolAddress(&ppart, g_part);
    cudaGetSymbolAddress(&plist, g_list);
    cudaGetSymbolAddress(&pcnt, g_cnt);

    cudaFuncSetAttribute(gemm1_kernel, cudaFuncAttributeMaxDynamicSharedMemorySize, SMEM_SZ);
    cudaFuncSetAttribute(gemm2_kernel, cudaFuncAttributeMaxDynamicSharedMemorySize, SMEM_SZ);

    gate_kernel<<<BB, 256>>>(x, Wg, bg, (float*)pgw);
    build_lists<<<NE, 256>>>((const float*)pgw, (int*)plist, (int*)pcnt);
    tohalf_kernel<<<2048, 256>>>(x, (__half*)px16, (size_t)BB * DD / 4);
    tohalf_kernel<<<16384, 256>>>(W1, (__half*)pw1h, (size_t)NE * HH * DD / 4);
    tohalf_kernel<<<16384, 256>>>(W2, (__half*)pw2h, (size_t)NE * OO * HH / 4);

    // layer 1: compacted tokens per expert
    gemm1_kernel<<<dim3(HH / 256, BB / 128, NE), TPB, SMEM_SZ>>>(
        (const __half*)px16, (const __half*)pw1h, b1, (const float*)pgw,
        (const int*)plist, (const int*)pcnt, (__half*)ph16);

    // layer 2: compacted rows, split-K=2, fp16 partials
    gemm2_kernel<<<dim3(OO / 256, BB / 128, 2 * NE), TPB, SMEM_SZ>>>(
        (const __half*)ph16, (const __half*)pw2h,
        (const int*)plist, (const int*)pcnt, (__half*)ppart);

    reduce_kernel<<<(BB * OO / 4 + 255) / 256, 256>>>(
        (const __half*)ppart, b2, (const float*)pgw, out);
}